// round 16
// baseline (speedup 1.0000x reference)
#include <cuda_runtime.h>
#include <cuda_fp16.h>
#include <cstdint>

// ---------------------------------------------------------------------------
// Problem constants
// ---------------------------------------------------------------------------
constexpr int BSZ = 2;
constexpr int L   = 2048;
constexpr int DM  = 1024;
constexpr int DIN = 2048;
constexpr int NST = 16;
constexpr int ROWS = BSZ * L;    // 4096
constexpr int NCH  = 16;         // scan chunks (proven)
constexpr int LC   = L / NCH;    // 128 steps per chunk
constexpr int N2   = 2176;       // combined delta|B|C|pad width (17*128)

// ---------------------------------------------------------------------------
// Scratch (static device globals)
// ---------------------------------------------------------------------------
__device__ __half g_xnh [(size_t)ROWS * DM];
__device__ __half g_xzh [(size_t)ROWS * 2 * DIN];
__device__ __half g_uh  [(size_t)ROWS * DIN];
__device__ float  g_delta[(size_t)ROWS * DIN];
__device__ float  g_Bseq [(size_t)ROWS * NST];
__device__ float  g_Cseq [(size_t)ROWS * NST];
__device__ __half g_gateh[(size_t)ROWS * DIN];
__device__ float  g_P    [(size_t)BSZ * DIN * NCH * NST];
__device__ float  g_hloc [(size_t)BSZ * DIN * NCH * NST];
__device__ float  g_H0   [(size_t)BSZ * DIN * NCH * NST];
// transposed fp16 weights ([N][K])
__device__ __half g_wtin [(size_t)(2 * DIN) * DM];
__device__ __half g_wtd2 [(size_t)N2 * DIN];        // [wdelta^T | wb^T | wc^T | 0]
__device__ __half g_wto  [(size_t)DM * DIN];

// ---------------------------------------------------------------------------
// Helpers
// ---------------------------------------------------------------------------
__device__ __forceinline__ uint32_t smem_u32(const void* p)
{
    uint32_t a;
    asm("{ .reg .u64 t; cvta.to.shared.u64 t, %1; cvt.u32.u64 %0, t; }"
        : "=r"(a) : "l"(p));
    return a;
}

__device__ __forceinline__ float softplusf(float v)
{
    return v > 20.f ? v : log1pf(expf(v));
}

#define CP_ASYNC16(dst, src) \
    asm volatile("cp.async.cg.shared.global [%0], [%1], 16;" \
                 :: "r"(dst), "l"(src) : "memory")
#define CP_COMMIT() asm volatile("cp.async.commit_group;" ::: "memory")
#define CP_WAIT1()  asm volatile("cp.async.wait_group 1;" ::: "memory")

#define LDMATRIX_X4(r0, r1, r2, r3, addr) \
    asm volatile("ldmatrix.sync.aligned.m8n8.x4.shared.b16 {%0,%1,%2,%3}, [%4];" \
                 : "=r"(r0), "=r"(r1), "=r"(r2), "=r"(r3) : "r"(addr))

#define MMA_F16(c0, c1, c2, c3, a0, a1, a2, a3, b0, b1) \
    asm volatile("mma.sync.aligned.m16n8k16.row.col.f32.f16.f16.f32 " \
                 "{%0,%1,%2,%3}, {%4,%5,%6,%7}, {%8,%9}, {%0,%1,%2,%3};" \
                 : "+f"(c0), "+f"(c1), "+f"(c2), "+f"(c3) \
                 : "r"(a0), "r"(a1), "r"(a2), "r"(a3), "r"(b0), "r"(b1))

// ---------------------------------------------------------------------------
// LayerNorm: one block per row; fp16 output
// ---------------------------------------------------------------------------
__global__ void ln_kernel(const float* __restrict__ x,
                          const float* __restrict__ w,
                          const float* __restrict__ b)
{
    __shared__ float sh[8];
    int row = blockIdx.x;
    const float* xr = x + (size_t)row * DM;
    int i0 = threadIdx.x * 4;
    float4 v = *(const float4*)(xr + i0);
    int lane = threadIdx.x & 31, wid = threadIdx.x >> 5;

    float s = v.x + v.y + v.z + v.w;
    #pragma unroll
    for (int o = 16; o > 0; o >>= 1) s += __shfl_down_sync(0xffffffffu, s, o);
    if (lane == 0) sh[wid] = s;
    __syncthreads();
    float t = (threadIdx.x < 8) ? sh[threadIdx.x] : 0.f;
    if (wid == 0) {
        #pragma unroll
        for (int o = 4; o > 0; o >>= 1) t += __shfl_down_sync(0xffffffffu, t, o);
        if (lane == 0) sh[0] = t;
    }
    __syncthreads();
    float mu = sh[0] * (1.f / DM);
    __syncthreads();

    float d0 = v.x - mu, d1 = v.y - mu, d2 = v.z - mu, d3 = v.w - mu;
    float ss = d0*d0 + d1*d1 + d2*d2 + d3*d3;
    #pragma unroll
    for (int o = 16; o > 0; o >>= 1) ss += __shfl_down_sync(0xffffffffu, ss, o);
    if (lane == 0) sh[wid] = ss;
    __syncthreads();
    t = (threadIdx.x < 8) ? sh[threadIdx.x] : 0.f;
    if (wid == 0) {
        #pragma unroll
        for (int o = 4; o > 0; o >>= 1) t += __shfl_down_sync(0xffffffffu, t, o);
        if (lane == 0) sh[0] = t;
    }
    __syncthreads();
    float rstd = rsqrtf(sh[0] * (1.f / DM) + 1e-5f);

    float4 wv = *(const float4*)(w + i0);
    float4 bv = *(const float4*)(b + i0);
    __half2 h0 = __floats2half2_rn(d0 * rstd * wv.x + bv.x, d1 * rstd * wv.y + bv.y);
    __half2 h1 = __floats2half2_rn(d2 * rstd * wv.z + bv.z, d3 * rstd * wv.w + bv.w);
    uint2 o2 = { *(uint32_t*)&h0, *(uint32_t*)&h1 };
    *(uint2*)(g_xnh + (size_t)row * DM + i0) = o2;
}

// ---------------------------------------------------------------------------
// Merged weight prep: all transposes (+fp16) and wb/wc pack in ONE kernel.
// ---------------------------------------------------------------------------
__device__ __forceinline__ void transpose_tile(float (*tile)[33],
                                               const float* __restrict__ in,
                                               __half* __restrict__ out,
                                               int R, int Cn, int ct, int rt,
                                               int tx, int ty)
{
    int c0 = ct * 32, r0 = rt * 32;
    #pragma unroll
    for (int i = 0; i < 4; i++)
        tile[ty + 8 * i][tx] = in[(size_t)(r0 + ty + 8 * i) * Cn + c0 + tx];
    __syncthreads();
    #pragma unroll
    for (int i = 0; i < 4; i++)
        out[(size_t)(c0 + ty + 8 * i) * R + r0 + tx] =
            __float2half_rn(tile[tx][ty + 8 * i]);
}

__global__ __launch_bounds__(256)
void prep_all_kernel(const float* __restrict__ w_in,
                     const float* __restrict__ w_delta,
                     const float* __restrict__ w_out,
                     const float* __restrict__ wb,
                     const float* __restrict__ wc)
{
    __shared__ float tile[32][33];
    int bid = blockIdx.x;
    int tx = threadIdx.x & 31, ty = threadIdx.x >> 5;

    if (bid < 4096) {
        transpose_tile(tile, w_in, g_wtin, DM, 2 * DIN, bid & 127, bid >> 7, tx, ty);
    } else if (bid < 8192) {
        int b = bid - 4096;
        transpose_tile(tile, w_delta, g_wtd2, DIN, DIN, b & 63, b >> 6, tx, ty);
    } else if (bid < 10240) {
        int b = bid - 8192;
        transpose_tile(tile, w_out, g_wto, DIN, DM, b & 31, b >> 5, tx, ty);
    } else {
        int k = (bid - 10240) * 256 + threadIdx.x;    // 0..2047
        #pragma unroll
        for (int n = 0; n < NST; n++) {
            g_wtd2[(size_t)(2048 + n) * DIN + k] = __float2half_rn(wb[(size_t)k * NST + n]);
            g_wtd2[(size_t)(2064 + n) * DIN + k] = __float2half_rn(wc[(size_t)k * NST + n]);
        }
        __half z = __float2half_rn(0.f);
        for (int n = 2080; n < N2; n++)
            g_wtd2[(size_t)n * DIN + k] = z;
    }
}

// ---------------------------------------------------------------------------
// FP16 mma.sync GEMM: 128 threads, 4 warps (2Mx2N), warp tile 64x64,
// BM=BN=128, BK=64, 3-stage cp.async (wait_group 1) -> half the barriers.
// smem: 3 * 36.9KB = 110.6KB/CTA -> 2 CTA/SM (221KB <= 228KB).
// EPI: 0 fp16 out (xz), 2 +residual fp32 out, 3 delta|Bseq|Cseq routing.
// ---------------------------------------------------------------------------
constexpr int BK     = 64;
constexpr int PADH   = 72;                        // smem row stride (halves)
constexpr int STG_H  = 2 * 128 * PADH;            // halves per stage (A+B)
constexpr int NSTG   = 3;
constexpr int GEMM_DSMEM = NSTG * STG_H * 2;      // 110592 bytes

template<int NTOT, int K, int EPI, int ASEL>
__global__ __launch_bounds__(128, 2)
void tc_gemm(const __half* __restrict__ Bt,
             const float* __restrict__ bias,
             const float* __restrict__ resid,
             float* __restrict__ Cext)
{
    const __half* A = (ASEL == 0) ? g_xnh : (ASEL == 1) ? g_uh : g_gateh;

    extern __shared__ __half dsm[];
    uint32_t smem0 = smem_u32(dsm);

    int tid = threadIdx.x;
    int lane = tid & 31, wid = tid >> 5;
    int wm = (wid & 1) * 64;
    int wn = (wid >> 1) * 64;
    int bm = blockIdx.y * 128;
    int bn = blockIdx.x * 128;
    int lr = lane & 3;
    int lg = lane >> 2;

    const __half* Ag0 = A  + (size_t)bm * K;
    const __half* Bg0 = Bt + (size_t)bn * K;

    // cp.async mapping: 8 q-steps x 128 thr = 1024 16B-chunks per operand
    // chunk f = q*128+tid: row = f>>3 (0..127), c16 = (f&7)*16 bytes
    int ld_row = tid >> 3;            // 0..15 (base; +16 per q)
    int ld_c16 = (tid & 7) * 16;      // byte offset in 128B row

    int a_lrow = ((lane >> 3) & 1) * 8 + (lane & 7);
    int a_lcol = (lane >> 4) * 8;
    int b_lrow = (lane >> 4) * 8 + (lane & 7);
    int b_lcol = ((lane >> 3) & 1) * 8;

    constexpr int KT = K / BK;

    auto issue = [&](int stage, int kt) {
        uint32_t sA = smem0 + (uint32_t)stage * STG_H * 2;
        uint32_t sB = sA + 128 * PADH * 2;
        const __half* Ag = Ag0 + kt * BK;
        const __half* Bg = Bg0 + kt * BK;
        #pragma unroll
        for (int q = 0; q < 8; q++) {
            int r = q * 16 + ld_row;
            CP_ASYNC16(sA + (uint32_t)(r * PADH * 2) + ld_c16,
                       (const char*)(Ag + (size_t)r * K) + ld_c16);
            CP_ASYNC16(sB + (uint32_t)(r * PADH * 2) + ld_c16,
                       (const char*)(Bg + (size_t)r * K) + ld_c16);
        }
    };

    float acc[4][8][4];
    #pragma unroll
    for (int i = 0; i < 4; i++)
        #pragma unroll
        for (int j = 0; j < 8; j++)
            #pragma unroll
            for (int q = 0; q < 4; q++) acc[i][j][q] = 0.f;

    issue(0, 0); CP_COMMIT();
    issue(1, 1); CP_COMMIT();

    for (int kt = 0; kt < KT; kt++) {
        CP_WAIT1();
        __syncthreads();

        uint32_t sA = smem0 + (uint32_t)(kt % NSTG) * STG_H * 2;
        uint32_t sB = sA + 128 * PADH * 2;

        #pragma unroll
        for (int kc = 0; kc < 4; kc++) {
            uint32_t af[4][4], bf[4][4];
            #pragma unroll
            for (int i = 0; i < 4; i++) {
                uint32_t a = sA + (uint32_t)((wm + 16 * i + a_lrow) * PADH
                                             + a_lcol + kc * 16) * 2;
                LDMATRIX_X4(af[i][0], af[i][1], af[i][2], af[i][3], a);
            }
            #pragma unroll
            for (int jj = 0; jj < 4; jj++) {
                uint32_t a = sB + (uint32_t)((wn + 16 * jj + b_lrow) * PADH
                                             + b_lcol + kc * 16) * 2;
                LDMATRIX_X4(bf[jj][0], bf[jj][1], bf[jj][2], bf[jj][3], a);
            }
            #pragma unroll
            for (int i = 0; i < 4; i++)
                #pragma unroll
                for (int jj = 0; jj < 4; jj++) {
                    MMA_F16(acc[i][2*jj][0], acc[i][2*jj][1],
                            acc[i][2*jj][2], acc[i][2*jj][3],
                            af[i][0], af[i][1], af[i][2], af[i][3],
                            bf[jj][0], bf[jj][1]);
                    MMA_F16(acc[i][2*jj+1][0], acc[i][2*jj+1][1],
                            acc[i][2*jj+1][2], acc[i][2*jj+1][3],
                            af[i][0], af[i][1], af[i][2], af[i][3],
                            bf[jj][2], bf[jj][3]);
                }
        }

        if (kt + 2 < KT) issue((kt + 2) % NSTG, kt + 2);
        CP_COMMIT();
    }

    // ---- epilogue ----
    #pragma unroll
    for (int i = 0; i < 4; i++) {
        int r0 = bm + wm + 16 * i + lg;
        #pragma unroll
        for (int j = 0; j < 8; j++) {
            int c0 = bn + wn + 8 * j + 2 * lr;
            float2 v0 = { acc[i][j][0], acc[i][j][1] };   // row r0
            float2 v1 = { acc[i][j][2], acc[i][j][3] };   // row r0+8
            if constexpr (EPI == 0) {
                __half2 h0 = __floats2half2_rn(v0.x, v0.y);
                __half2 h1 = __floats2half2_rn(v1.x, v1.y);
                *(uint32_t*)(g_xzh + (size_t)r0 * NTOT + c0) = *(uint32_t*)&h0;
                *(uint32_t*)(g_xzh + (size_t)(r0 + 8) * NTOT + c0) = *(uint32_t*)&h1;
            } else if constexpr (EPI == 3) {
                if (c0 < DIN) {
                    float b0 = bias[c0], b1 = bias[c0 + 1];
                    v0.x = softplusf(v0.x + b0); v0.y = softplusf(v0.y + b1);
                    v1.x = softplusf(v1.x + b0); v1.y = softplusf(v1.y + b1);
                    *(float2*)(g_delta + (size_t)r0 * DIN + c0) = v0;
                    *(float2*)(g_delta + (size_t)(r0 + 8) * DIN + c0) = v1;
                } else if (c0 < DIN + NST) {
                    int n = c0 - DIN;
                    *(float2*)(g_Bseq + (size_t)r0 * NST + n) = v0;
                    *(float2*)(g_Bseq + (size_t)(r0 + 8) * NST + n) = v1;
                } else if (c0 < DIN + 2 * NST) {
                    int n = c0 - DIN - NST;
                    *(float2*)(g_Cseq + (size_t)r0 * NST + n) = v0;
                    *(float2*)(g_Cseq + (size_t)(r0 + 8) * NST + n) = v1;
                }
            } else {
                float2 ra = *(const float2*)(resid + (size_t)r0 * NTOT + c0);
                float2 rb = *(const float2*)(resid + (size_t)(r0 + 8) * NTOT + c0);
                v0.x += ra.x; v0.y += ra.y;
                v1.x += rb.x; v1.y += rb.y;
                *(float2*)(Cext + (size_t)r0 * NTOT + c0) = v0;
                *(float2*)(Cext + (size_t)(r0 + 8) * NTOT + c0) = v1;
            }
        }
    }
}

// ---------------------------------------------------------------------------
// Depthwise causal conv1d + bias + SiLU: rolling window, 4 rows/thread,
// 4 channels/thread (proven R15 config).
// ---------------------------------------------------------------------------
constexpr int CRPT = 4;    // rows per thread
constexpr int CCH  = 4;    // channels per thread

__global__ void conv_silu_kernel(const float* __restrict__ wconv,
                                 const float* __restrict__ bconv)
{
    int t = blockIdx.x * blockDim.x + threadIdx.x;
    int dg = t & (DIN / CCH - 1);
    int d0 = dg * CCH;
    int rb = t >> 9;
    int row0 = rb * CRPT;
    int l0 = row0 & (L - 1);

    float w0[CCH], w1[CCH], w2[CCH], w3[CCH], bs[CCH];
    #pragma unroll
    for (int c = 0; c < CCH; c++) {
        float4 w4 = *(const float4*)(wconv + (size_t)(d0 + c) * 4);
        w0[c] = w4.x; w1[c] = w4.y; w2[c] = w4.z; w3[c] = w4.w;
        bs[c] = bconv[d0 + c];
    }

    float win[3][CCH];
    #pragma unroll
    for (int j = 0; j < 3; j++) {
        int loff = l0 - 3 + j;
        if (loff >= 0) {
            uint2 r2 = *(const uint2*)(g_xzh + (size_t)(row0 - 3 + j) * (2 * DIN) + d0);
            const __half2* hp = (const __half2*)&r2;
            #pragma unroll
            for (int q = 0; q < 2; q++) {
                float2 f2 = __half22float2(hp[q]);
                win[j][2*q]   = f2.x;
                win[j][2*q+1] = f2.y;
            }
        } else {
            #pragma unroll
            for (int q = 0; q < CCH; q++) win[j][q] = 0.f;
        }
    }

    #pragma unroll
    for (int it = 0; it < CRPT; it++) {
        int row = row0 + it;
        float cur[CCH];
        {
            uint2 r2 = *(const uint2*)(g_xzh + (size_t)row * (2 * DIN) + d0);
            const __half2* hp = (const __half2*)&r2;
            #pragma unroll
            for (int q = 0; q < 2; q++) {
                float2 f2 = __half22float2(hp[q]);
                cur[2*q]   = f2.x;
                cur[2*q+1] = f2.y;
            }
        }

        __half hout[CCH];
        #pragma unroll
        for (int c = 0; c < CCH; c++) {
            float s = bs[c];
            s = fmaf(win[0][c], w0[c], s);
            s = fmaf(win[1][c], w1[c], s);
            s = fmaf(win[2][c], w2[c], s);
            s = fmaf(cur[c],    w3[c], s);
            float sig = 1.f / (1.f + __expf(-s));
            hout[c] = __float2half_rn(s * sig);
        }
        *(uint2*)(g_uh + (size_t)row * DIN + d0) = *(uint2*)hout;

        #pragma unroll
        for (int q = 0; q < CCH; q++) {
            win[0][q] = win[1][q];
            win[1][q] = win[2][q];
            win[2][q] = cur[q];
        }
    }
}

// ---------------------------------------------------------------------------
// Chunked selective scan with SMEM-staged B/C tiles (proven R15 config).
// 128-thread blocks over 128-wide d-slabs; pass1 closed-form P (structured).
// ---------------------------------------------------------------------------
template<bool PASS2>
__global__ __launch_bounds__(128)
void scan_kernel(const float* __restrict__ A_log,
                 const float* __restrict__ D_param)
{
    __shared__ float sB[LC][NST];
    __shared__ float sC[PASS2 ? LC : 1][NST];

    int tid = threadIdx.x;
    int dblk = blockIdx.x & 15;
    int c = (blockIdx.x >> 4) & (NCH - 1);
    int b = blockIdx.x >> 8;
    int d = dblk * 128 + tid;

    size_t row0 = (size_t)b * L + (size_t)c * LC;

    #pragma unroll
    for (int q = 0; q < 4; q++) {
        int flat = q * 128 + tid;
        int t = flat >> 2, n4 = (flat & 3) * 4;
        *(float4*)&sB[t][n4] = *(const float4*)(g_Bseq + (row0 + t) * NST + n4);
        if constexpr (PASS2)
            *(float4*)&sC[t][n4] = *(const float4*)(g_Cseq + (row0 + t) * NST + n4);
    }
    __syncthreads();

    float A[NST];
    #pragma unroll
    for (int n = 0; n < NST; n += 4) {
        float4 v = *(const float4*)(A_log + (size_t)d * NST + n);
        A[n]   = -__expf(v.x);
        A[n+1] = -__expf(v.y);
        A[n+2] = -__expf(v.z);
        A[n+3] = -__expf(v.w);
    }

    bool structured = true;
    #pragma unroll
    for (int n = 1; n < NST; n++) {
        float t = (float)(n + 1) * A[0];
        if (fabsf(A[n] - t) > 1e-4f * fabsf(t)) structured = false;
    }

    float h[NST], P[NST];
    #pragma unroll
    for (int n = 0; n < NST; n++) { h[n] = 0.f; P[n] = 1.f; }
    float sdl = 0.f;

    size_t sidx = ((size_t)((b * DIN + d) * NCH + c)) * NST;
    if constexpr (PASS2) {
        #pragma unroll
        for (int n = 0; n < NST; n += 4) {
            float4 v = *(const float4*)(g_H0 + sidx + n);
            h[n] = v.x; h[n+1] = v.y; h[n+2] = v.z; h[n+3] = v.w;
        }
    }
    float Dp = PASS2 ? D_param[d] : 0.f;

    for (int t = 0; t < LC; t++) {
        size_t row = row0 + t;
        float dl = g_delta[row * DIN + d];
        float uv = __half2float(g_uh[row * DIN + d]);
        float du = dl * uv;

        float e[NST];
        if (structured) {
            float e1 = __expf(dl * A[0]);
            float e2 = e1 * e1, e4 = e2 * e2, e8 = e4 * e4;
            e[0]  = e1;           e[1]  = e2;           e[2]  = e2 * e1;
            e[3]  = e4;           e[4]  = e4 * e1;      e[5]  = e4 * e2;
            e[6]  = e4 * e2 * e1; e[7]  = e8;           e[8]  = e8 * e1;
            e[9]  = e8 * e2;      e[10] = e8 * e2 * e1; e[11] = e8 * e4;
            e[12] = e8 * e4 * e1; e[13] = e8 * e4 * e2; e[14] = e8 * e4 * e2 * e1;
            e[15] = e8 * e8;
            if constexpr (!PASS2) sdl += dl;
        } else {
            #pragma unroll
            for (int n = 0; n < NST; n++) e[n] = __expf(dl * A[n]);
            if constexpr (!PASS2) {
                #pragma unroll
                for (int n = 0; n < NST; n++) P[n] *= e[n];
            }
        }

        #pragma unroll
        for (int n = 0; n < NST; n++)
            h[n] = fmaf(e[n], h[n], du * sB[t][n]);

        if constexpr (PASS2) {
            float y = Dp * uv;
            #pragma unroll
            for (int n = 0; n < NST; n++) y = fmaf(h[n], sC[t][n], y);

            float z = __half2float(g_xzh[row * (size_t)(2 * DIN) + DIN + d]);
            float sz = z / (1.f + __expf(-z));
            g_gateh[row * DIN + d] = __float2half_rn(y * sz);
        }
    }

    if constexpr (!PASS2) {
        if (structured) {
            float p1 = __expf(sdl * A[0]);
            float p2 = p1 * p1, p4 = p2 * p2, p8 = p4 * p4;
            P[0]  = p1;           P[1]  = p2;           P[2]  = p2 * p1;
            P[3]  = p4;           P[4]  = p4 * p1;      P[5]  = p4 * p2;
            P[6]  = p4 * p2 * p1; P[7]  = p8;           P[8]  = p8 * p1;
            P[9]  = p8 * p2;      P[10] = p8 * p2 * p1; P[11] = p8 * p4;
            P[12] = p8 * p4 * p1; P[13] = p8 * p4 * p2; P[14] = p8 * p4 * p2 * p1;
            P[15] = p8 * p8;
        }
        #pragma unroll
        for (int n = 0; n < NST; n += 4) {
            float4 vp = { P[n], P[n+1], P[n+2], P[n+3] };
            float4 vh = { h[n], h[n+1], h[n+2], h[n+3] };
            *(float4*)(g_P + sidx + n)    = vp;
            *(float4*)(g_hloc + sidx + n) = vh;
        }
    }
}

__global__ void scan_combine_kernel()
{
    int gid = blockIdx.x * blockDim.x + threadIdx.x;
    if (gid >= BSZ * DIN) return;
    size_t base = (size_t)gid * NCH * NST;
    float H[NST];
    #pragma unroll
    for (int n = 0; n < NST; n++) H[n] = 0.f;
    for (int c = 0; c < NCH; c++) {
        size_t idx = base + (size_t)c * NST;
        #pragma unroll
        for (int n = 0; n < NST; n += 4) {
            float4 v = { H[n], H[n+1], H[n+2], H[n+3] };
            *(float4*)(g_H0 + idx + n) = v;
        }
        #pragma unroll
        for (int n = 0; n < NST; n++)
            H[n] = fmaf(g_P[idx + n], H[n], g_hloc[idx + n]);
    }
}

// ---------------------------------------------------------------------------
// Launch
// ---------------------------------------------------------------------------
extern "C" void kernel_launch(void* const* d_in, const int* in_sizes, int n_in,
                              void* d_out, int out_size)
{
    const float* x       = (const float*)d_in[0];
    const float* w_norm  = (const float*)d_in[1];
    const float* b_norm  = (const float*)d_in[2];
    const float* w_in    = (const float*)d_in[3];
    const float* w_conv  = (const float*)d_in[4];
    const float* b_conv  = (const float*)d_in[5];
    const float* A_log   = (const float*)d_in[6];
    const float* w_b     = (const float*)d_in[7];
    const float* w_c     = (const float*)d_in[8];
    const float* w_delta = (const float*)d_in[9];
    const float* b_delta = (const float*)d_in[10];
    const float* D_param = (const float*)d_in[11];
    const float* w_out   = (const float*)d_in[12];
    float* out = (float*)d_out;

    cudaFuncSetAttribute(tc_gemm<2 * DIN, DM, 0, 0>,
                         cudaFuncAttributeMaxDynamicSharedMemorySize, GEMM_DSMEM);
    cudaFuncSetAttribute(tc_gemm<N2, DIN, 3, 1>,
                         cudaFuncAttributeMaxDynamicSharedMemorySize, GEMM_DSMEM);
    cudaFuncSetAttribute(tc_gemm<DM, DIN, 2, 2>,
                         cudaFuncAttributeMaxDynamicSharedMemorySize, GEMM_DSMEM);

    __half *wt_in, *wt_d2, *wt_o;
    cudaGetSymbolAddress((void**)&wt_in, g_wtin);
    cudaGetSymbolAddress((void**)&wt_d2, g_wtd2);
    cudaGetSymbolAddress((void**)&wt_o,  g_wto);

    // 0. merged weight prep
    prep_all_kernel<<<10248, 256>>>(w_in, w_delta, w_out, w_b, w_c);

    // 1. LayerNorm (fp16 out)
    ln_kernel<<<ROWS, 256>>>(x, w_norm, b_norm);

    // 2. xz = xn @ w_in  (fp16 out)
    tc_gemm<2 * DIN, DM, 0, 0>
        <<<dim3((2 * DIN) / 128, ROWS / 128), 128, GEMM_DSMEM>>>(wt_in, nullptr, nullptr, nullptr);

    // 3. conv + silu -> uh
    conv_silu_kernel<<<(ROWS / CRPT) * (DIN / CCH) / 256, 256>>>(w_conv, b_conv);

    // 4. combined: delta = softplus(u@w_delta + b), Bseq, Cseq
    tc_gemm<N2, DIN, 3, 1>
        <<<dim3(N2 / 128, ROWS / 128), 128, GEMM_DSMEM>>>(wt_d2, b_delta, nullptr, nullptr);

    // 5. chunked selective scan
    scan_kernel<false><<<BSZ * NCH * (DIN / 128), 128>>>(A_log, D_param);
    scan_combine_kernel<<<(BSZ * DIN) / 256, 256>>>();
    scan_kernel<true><<<BSZ * NCH * (DIN / 128), 128>>>(A_log, D_param);

    // 6. out = gate @ w_out + residual
    tc_gemm<DM, DIN, 2, 2>
        <<<dim3(DM / 128, ROWS / 128), 128, GEMM_DSMEM>>>(wt_o, nullptr, x, out);
}

// round 17
// speedup vs baseline: 1.0583x; 1.0583x over previous
#include <cuda_runtime.h>
#include <cuda_fp16.h>
#include <cstdint>

// ---------------------------------------------------------------------------
// Problem constants
// ---------------------------------------------------------------------------
constexpr int BSZ = 2;
constexpr int L   = 2048;
constexpr int DM  = 1024;
constexpr int DIN = 2048;
constexpr int NST = 16;
constexpr int ROWS = BSZ * L;    // 4096
constexpr int NCH  = 16;         // scan chunks (proven)
constexpr int LC   = L / NCH;    // 128 steps per chunk
constexpr int N2   = 2176;       // combined delta|B|C|pad width (17*128)

// ---------------------------------------------------------------------------
// Scratch (static device globals)
// ---------------------------------------------------------------------------
__device__ __half g_xnh [(size_t)ROWS * DM];
__device__ __half g_xzh [(size_t)ROWS * 2 * DIN];
__device__ __half g_uh  [(size_t)ROWS * DIN];
__device__ float  g_delta[(size_t)ROWS * DIN];
__device__ float  g_Bseq [(size_t)ROWS * NST];
__device__ float  g_Cseq [(size_t)ROWS * NST];
__device__ __half g_gateh[(size_t)ROWS * DIN];
__device__ float  g_P    [(size_t)BSZ * DIN * NCH * NST];
__device__ float  g_hloc [(size_t)BSZ * DIN * NCH * NST];
__device__ float  g_H0   [(size_t)BSZ * DIN * NCH * NST];
// transposed fp16 weights ([N][K])
__device__ __half g_wtin [(size_t)(2 * DIN) * DM];
__device__ __half g_wtd2 [(size_t)N2 * DIN];        // [wdelta^T | wb^T | wc^T | 0]
__device__ __half g_wto  [(size_t)DM * DIN];

// ---------------------------------------------------------------------------
// Helpers
// ---------------------------------------------------------------------------
__device__ __forceinline__ uint32_t smem_u32(const void* p)
{
    uint32_t a;
    asm("{ .reg .u64 t; cvta.to.shared.u64 t, %1; cvt.u32.u64 %0, t; }"
        : "=r"(a) : "l"(p));
    return a;
}

__device__ __forceinline__ float softplusf(float v)
{
    return v > 20.f ? v : log1pf(expf(v));
}

#define CP_ASYNC16(dst, src) \
    asm volatile("cp.async.cg.shared.global [%0], [%1], 16;" \
                 :: "r"(dst), "l"(src) : "memory")
#define CP_COMMIT() asm volatile("cp.async.commit_group;" ::: "memory")
#define CP_WAIT2()  asm volatile("cp.async.wait_group 2;" ::: "memory")

#define LDMATRIX_X4(r0, r1, r2, r3, addr) \
    asm volatile("ldmatrix.sync.aligned.m8n8.x4.shared.b16 {%0,%1,%2,%3}, [%4];" \
                 : "=r"(r0), "=r"(r1), "=r"(r2), "=r"(r3) : "r"(addr))

#define MMA_F16(c0, c1, c2, c3, a0, a1, a2, a3, b0, b1) \
    asm volatile("mma.sync.aligned.m16n8k16.row.col.f32.f16.f16.f32 " \
                 "{%0,%1,%2,%3}, {%4,%5,%6,%7}, {%8,%9}, {%0,%1,%2,%3};" \
                 : "+f"(c0), "+f"(c1), "+f"(c2), "+f"(c3) \
                 : "r"(a0), "r"(a1), "r"(a2), "r"(a3), "r"(b0), "r"(b1))

// ---------------------------------------------------------------------------
// Merged prep + layernorm kernel:
//   blocks [0, 4096)      : w_in transpose    -> g_wtin
//   blocks [4096, 8192)   : w_delta transpose -> g_wtd2 rows 0..2047
//   blocks [8192, 10240)  : w_out transpose   -> g_wto
//   blocks [10240, 10248) : wb/wc pack        -> g_wtd2 rows 2048.., zero pad
//   blocks [10248, 14344) : layernorm row (bid - 10248) -> g_xnh
// All groups independent; co-execute in one launch.
// ---------------------------------------------------------------------------
__device__ __forceinline__ void transpose_tile(float (*tile)[33],
                                               const float* __restrict__ in,
                                               __half* __restrict__ out,
                                               int R, int Cn, int ct, int rt,
                                               int tx, int ty)
{
    int c0 = ct * 32, r0 = rt * 32;
    #pragma unroll
    for (int i = 0; i < 4; i++)
        tile[ty + 8 * i][tx] = in[(size_t)(r0 + ty + 8 * i) * Cn + c0 + tx];
    __syncthreads();
    #pragma unroll
    for (int i = 0; i < 4; i++)
        out[(size_t)(c0 + ty + 8 * i) * R + r0 + tx] =
            __float2half_rn(tile[tx][ty + 8 * i]);
}

__device__ __forceinline__ void ln_row(float* sh, int row,
                                       const float* __restrict__ x,
                                       const float* __restrict__ w,
                                       const float* __restrict__ b)
{
    const float* xr = x + (size_t)row * DM;
    int i0 = threadIdx.x * 4;
    float4 v = *(const float4*)(xr + i0);
    int lane = threadIdx.x & 31, wid = threadIdx.x >> 5;

    float s = v.x + v.y + v.z + v.w;
    #pragma unroll
    for (int o = 16; o > 0; o >>= 1) s += __shfl_down_sync(0xffffffffu, s, o);
    if (lane == 0) sh[wid] = s;
    __syncthreads();
    float t = (threadIdx.x < 8) ? sh[threadIdx.x] : 0.f;
    if (wid == 0) {
        #pragma unroll
        for (int o = 4; o > 0; o >>= 1) t += __shfl_down_sync(0xffffffffu, t, o);
        if (lane == 0) sh[0] = t;
    }
    __syncthreads();
    float mu = sh[0] * (1.f / DM);
    __syncthreads();

    float d0 = v.x - mu, d1 = v.y - mu, d2 = v.z - mu, d3 = v.w - mu;
    float ss = d0*d0 + d1*d1 + d2*d2 + d3*d3;
    #pragma unroll
    for (int o = 16; o > 0; o >>= 1) ss += __shfl_down_sync(0xffffffffu, ss, o);
    if (lane == 0) sh[wid] = ss;
    __syncthreads();
    t = (threadIdx.x < 8) ? sh[threadIdx.x] : 0.f;
    if (wid == 0) {
        #pragma unroll
        for (int o = 4; o > 0; o >>= 1) t += __shfl_down_sync(0xffffffffu, t, o);
        if (lane == 0) sh[0] = t;
    }
    __syncthreads();
    float rstd = rsqrtf(sh[0] * (1.f / DM) + 1e-5f);

    float4 wv = *(const float4*)(w + i0);
    float4 bv = *(const float4*)(b + i0);
    __half2 h0 = __floats2half2_rn(d0 * rstd * wv.x + bv.x, d1 * rstd * wv.y + bv.y);
    __half2 h1 = __floats2half2_rn(d2 * rstd * wv.z + bv.z, d3 * rstd * wv.w + bv.w);
    uint2 o2 = { *(uint32_t*)&h0, *(uint32_t*)&h1 };
    *(uint2*)(g_xnh + (size_t)row * DM + i0) = o2;
}

__global__ __launch_bounds__(256)
void prep_ln_kernel(const float* __restrict__ w_in,
                    const float* __restrict__ w_delta,
                    const float* __restrict__ w_out,
                    const float* __restrict__ wb,
                    const float* __restrict__ wc,
                    const float* __restrict__ x,
                    const float* __restrict__ w_norm,
                    const float* __restrict__ b_norm)
{
    __shared__ float tile[32][33];
    int bid = blockIdx.x;
    int tx = threadIdx.x & 31, ty = threadIdx.x >> 5;

    if (bid < 4096) {
        transpose_tile(tile, w_in, g_wtin, DM, 2 * DIN, bid & 127, bid >> 7, tx, ty);
    } else if (bid < 8192) {
        int b = bid - 4096;
        transpose_tile(tile, w_delta, g_wtd2, DIN, DIN, b & 63, b >> 6, tx, ty);
    } else if (bid < 10240) {
        int b = bid - 8192;
        transpose_tile(tile, w_out, g_wto, DIN, DM, b & 31, b >> 5, tx, ty);
    } else if (bid < 10248) {
        int k = (bid - 10240) * 256 + threadIdx.x;    // 0..2047
        #pragma unroll
        for (int n = 0; n < NST; n++) {
            g_wtd2[(size_t)(2048 + n) * DIN + k] = __float2half_rn(wb[(size_t)k * NST + n]);
            g_wtd2[(size_t)(2064 + n) * DIN + k] = __float2half_rn(wc[(size_t)k * NST + n]);
        }
        __half z = __float2half_rn(0.f);
        for (int n = 2080; n < N2; n++)
            g_wtd2[(size_t)n * DIN + k] = z;
    } else {
        ln_row(&tile[0][0], bid - 10248, x, w_norm, b_norm);
    }
}

// ---------------------------------------------------------------------------
// FP16 mma.sync GEMM (proven R15 config): 128 threads, 4 warps (2Mx2N),
// warp tile 64x64, BM=BN=128, BK=32, 4-stage cp.async (wait_group 2).
// EPI: 0 fp16 out (xz), 2 +residual fp32 out, 3 delta|Bseq|Cseq routing.
// ---------------------------------------------------------------------------
constexpr int PADH   = 40;                        // smem row stride (halves)
constexpr int STG_H  = 2 * 128 * PADH;            // halves per stage (A+B)
constexpr int NSTG   = 4;
constexpr int GEMM_DSMEM = NSTG * STG_H * 2;      // 81920 bytes

template<int NTOT, int K, int EPI, int ASEL>
__global__ __launch_bounds__(128, 2)
void tc_gemm(const __half* __restrict__ Bt,
             const float* __restrict__ bias,
             const float* __restrict__ resid,
             float* __restrict__ Cext)
{
    const __half* A = (ASEL == 0) ? g_xnh : (ASEL == 1) ? g_uh : g_gateh;

    extern __shared__ __half dsm[];
    uint32_t smem0 = smem_u32(dsm);

    int tid = threadIdx.x;
    int lane = tid & 31, wid = tid >> 5;
    int wm = (wid & 1) * 64;
    int wn = (wid >> 1) * 64;
    int bm = blockIdx.y * 128;
    int bn = blockIdx.x * 128;
    int lr = lane & 3;
    int lg = lane >> 2;

    const __half* Ag0 = A  + (size_t)bm * K;
    const __half* Bg0 = Bt + (size_t)bn * K;

    int ld_row = tid >> 2;            // 0..31
    int ld_c16 = (tid & 3) * 16;      // byte offset in 64B row

    int a_lrow = ((lane >> 3) & 1) * 8 + (lane & 7);
    int a_lcol = (lane >> 4) * 8;
    int b_lrow = (lane >> 4) * 8 + (lane & 7);
    int b_lcol = ((lane >> 3) & 1) * 8;

    constexpr int KT = K / 32;

    auto issue = [&](int stage, int kt) {
        uint32_t sA = smem0 + (uint32_t)stage * STG_H * 2;
        uint32_t sB = sA + 128 * PADH * 2;
        const __half* Ag = Ag0 + kt * 32;
        const __half* Bg = Bg0 + kt * 32;
        #pragma unroll
        for (int q = 0; q < 4; q++) {
            int r = q * 32 + ld_row;
            CP_ASYNC16(sA + (uint32_t)(r * PADH * 2) + ld_c16,
                       (const char*)(Ag + (size_t)r * K) + ld_c16);
            CP_ASYNC16(sB + (uint32_t)(r * PADH * 2) + ld_c16,
                       (const char*)(Bg + (size_t)r * K) + ld_c16);
        }
    };

    float acc[4][8][4];
    #pragma unroll
    for (int i = 0; i < 4; i++)
        #pragma unroll
        for (int j = 0; j < 8; j++)
            #pragma unroll
            for (int q = 0; q < 4; q++) acc[i][j][q] = 0.f;

    issue(0, 0); CP_COMMIT();
    issue(1, 1); CP_COMMIT();
    issue(2, 2); CP_COMMIT();

    for (int kt = 0; kt < KT; kt++) {
        CP_WAIT2();
        __syncthreads();

        uint32_t sA = smem0 + (uint32_t)(kt % NSTG) * STG_H * 2;
        uint32_t sB = sA + 128 * PADH * 2;

        #pragma unroll
        for (int kc = 0; kc < 2; kc++) {
            uint32_t af[4][4], bf[4][4];
            #pragma unroll
            for (int i = 0; i < 4; i++) {
                uint32_t a = sA + (uint32_t)((wm + 16 * i + a_lrow) * PADH
                                             + a_lcol + kc * 16) * 2;
                LDMATRIX_X4(af[i][0], af[i][1], af[i][2], af[i][3], a);
            }
            #pragma unroll
            for (int jj = 0; jj < 4; jj++) {
                uint32_t a = sB + (uint32_t)((wn + 16 * jj + b_lrow) * PADH
                                             + b_lcol + kc * 16) * 2;
                LDMATRIX_X4(bf[jj][0], bf[jj][1], bf[jj][2], bf[jj][3], a);
            }
            #pragma unroll
            for (int i = 0; i < 4; i++)
                #pragma unroll
                for (int jj = 0; jj < 4; jj++) {
                    MMA_F16(acc[i][2*jj][0], acc[i][2*jj][1],
                            acc[i][2*jj][2], acc[i][2*jj][3],
                            af[i][0], af[i][1], af[i][2], af[i][3],
                            bf[jj][0], bf[jj][1]);
                    MMA_F16(acc[i][2*jj+1][0], acc[i][2*jj+1][1],
                            acc[i][2*jj+1][2], acc[i][2*jj+1][3],
                            af[i][0], af[i][1], af[i][2], af[i][3],
                            bf[jj][2], bf[jj][3]);
                }
        }

        if (kt + 3 < KT) issue((kt + 3) % NSTG, kt + 3);
        CP_COMMIT();
    }

    // ---- epilogue ----
    #pragma unroll
    for (int i = 0; i < 4; i++) {
        int r0 = bm + wm + 16 * i + lg;
        #pragma unroll
        for (int j = 0; j < 8; j++) {
            int c0 = bn + wn + 8 * j + 2 * lr;
            float2 v0 = { acc[i][j][0], acc[i][j][1] };   // row r0
            float2 v1 = { acc[i][j][2], acc[i][j][3] };   // row r0+8
            if constexpr (EPI == 0) {
                __half2 h0 = __floats2half2_rn(v0.x, v0.y);
                __half2 h1 = __floats2half2_rn(v1.x, v1.y);
                *(uint32_t*)(g_xzh + (size_t)r0 * NTOT + c0) = *(uint32_t*)&h0;
                *(uint32_t*)(g_xzh + (size_t)(r0 + 8) * NTOT + c0) = *(uint32_t*)&h1;
            } else if constexpr (EPI == 3) {
                if (c0 < DIN) {
                    float b0 = bias[c0], b1 = bias[c0 + 1];
                    v0.x = softplusf(v0.x + b0); v0.y = softplusf(v0.y + b1);
                    v1.x = softplusf(v1.x + b0); v1.y = softplusf(v1.y + b1);
                    *(float2*)(g_delta + (size_t)r0 * DIN + c0) = v0;
                    *(float2*)(g_delta + (size_t)(r0 + 8) * DIN + c0) = v1;
                } else if (c0 < DIN + NST) {
                    int n = c0 - DIN;
                    *(float2*)(g_Bseq + (size_t)r0 * NST + n) = v0;
                    *(float2*)(g_Bseq + (size_t)(r0 + 8) * NST + n) = v1;
                } else if (c0 < DIN + 2 * NST) {
                    int n = c0 - DIN - NST;
                    *(float2*)(g_Cseq + (size_t)r0 * NST + n) = v0;
                    *(float2*)(g_Cseq + (size_t)(r0 + 8) * NST + n) = v1;
                }
            } else {
                float2 ra = *(const float2*)(resid + (size_t)r0 * NTOT + c0);
                float2 rb = *(const float2*)(resid + (size_t)(r0 + 8) * NTOT + c0);
                v0.x += ra.x; v0.y += ra.y;
                v1.x += rb.x; v1.y += rb.y;
                *(float2*)(Cext + (size_t)r0 * NTOT + c0) = v0;
                *(float2*)(Cext + (size_t)(r0 + 8) * NTOT + c0) = v1;
            }
        }
    }
}

// ---------------------------------------------------------------------------
// Depthwise causal conv1d + bias + SiLU: rolling window, 4 rows/thread,
// 4 channels/thread (proven R15 config).
// ---------------------------------------------------------------------------
constexpr int CRPT = 4;    // rows per thread
constexpr int CCH  = 4;    // channels per thread

__global__ void conv_silu_kernel(const float* __restrict__ wconv,
                                 const float* __restrict__ bconv)
{
    int t = blockIdx.x * blockDim.x + threadIdx.x;
    int dg = t & (DIN / CCH - 1);
    int d0 = dg * CCH;
    int rb = t >> 9;
    int row0 = rb * CRPT;
    int l0 = row0 & (L - 1);

    float w0[CCH], w1[CCH], w2[CCH], w3[CCH], bs[CCH];
    #pragma unroll
    for (int c = 0; c < CCH; c++) {
        float4 w4 = *(const float4*)(wconv + (size_t)(d0 + c) * 4);
        w0[c] = w4.x; w1[c] = w4.y; w2[c] = w4.z; w3[c] = w4.w;
        bs[c] = bconv[d0 + c];
    }

    float win[3][CCH];
    #pragma unroll
    for (int j = 0; j < 3; j++) {
        int loff = l0 - 3 + j;
        if (loff >= 0) {
            uint2 r2 = *(const uint2*)(g_xzh + (size_t)(row0 - 3 + j) * (2 * DIN) + d0);
            const __half2* hp = (const __half2*)&r2;
            #pragma unroll
            for (int q = 0; q < 2; q++) {
                float2 f2 = __half22float2(hp[q]);
                win[j][2*q]   = f2.x;
                win[j][2*q+1] = f2.y;
            }
        } else {
            #pragma unroll
            for (int q = 0; q < CCH; q++) win[j][q] = 0.f;
        }
    }

    #pragma unroll
    for (int it = 0; it < CRPT; it++) {
        int row = row0 + it;
        float cur[CCH];
        {
            uint2 r2 = *(const uint2*)(g_xzh + (size_t)row * (2 * DIN) + d0);
            const __half2* hp = (const __half2*)&r2;
            #pragma unroll
            for (int q = 0; q < 2; q++) {
                float2 f2 = __half22float2(hp[q]);
                cur[2*q]   = f2.x;
                cur[2*q+1] = f2.y;
            }
        }

        __half hout[CCH];
        #pragma unroll
        for (int c = 0; c < CCH; c++) {
            float s = bs[c];
            s = fmaf(win[0][c], w0[c], s);
            s = fmaf(win[1][c], w1[c], s);
            s = fmaf(win[2][c], w2[c], s);
            s = fmaf(cur[c],    w3[c], s);
            float sig = 1.f / (1.f + __expf(-s));
            hout[c] = __float2half_rn(s * sig);
        }
        *(uint2*)(g_uh + (size_t)row * DIN + d0) = *(uint2*)hout;

        #pragma unroll
        for (int q = 0; q < CCH; q++) {
            win[0][q] = win[1][q];
            win[1][q] = win[2][q];
            win[2][q] = cur[q];
        }
    }
}

// ---------------------------------------------------------------------------
// Chunked selective scan with SMEM-staged B/C tiles (proven R15 config).
// 128-thread blocks over 128-wide d-slabs; pass1 closed-form P (structured).
// ---------------------------------------------------------------------------
template<bool PASS2>
__global__ __launch_bounds__(128)
void scan_kernel(const float* __restrict__ A_log,
                 const float* __restrict__ D_param)
{
    __shared__ float sB[LC][NST];
    __shared__ float sC[PASS2 ? LC : 1][NST];

    int tid = threadIdx.x;
    int dblk = blockIdx.x & 15;
    int c = (blockIdx.x >> 4) & (NCH - 1);
    int b = blockIdx.x >> 8;
    int d = dblk * 128 + tid;

    size_t row0 = (size_t)b * L + (size_t)c * LC;

    #pragma unroll
    for (int q = 0; q < 4; q++) {
        int flat = q * 128 + tid;
        int t = flat >> 2, n4 = (flat & 3) * 4;
        *(float4*)&sB[t][n4] = *(const float4*)(g_Bseq + (row0 + t) * NST + n4);
        if constexpr (PASS2)
            *(float4*)&sC[t][n4] = *(const float4*)(g_Cseq + (row0 + t) * NST + n4);
    }
    __syncthreads();

    float A[NST];
    #pragma unroll
    for (int n = 0; n < NST; n += 4) {
        float4 v = *(const float4*)(A_log + (size_t)d * NST + n);
        A[n]   = -__expf(v.x);
        A[n+1] = -__expf(v.y);
        A[n+2] = -__expf(v.z);
        A[n+3] = -__expf(v.w);
    }

    bool structured = true;
    #pragma unroll
    for (int n = 1; n < NST; n++) {
        float t = (float)(n + 1) * A[0];
        if (fabsf(A[n] - t) > 1e-4f * fabsf(t)) structured = false;
    }

    float h[NST], P[NST];
    #pragma unroll
    for (int n = 0; n < NST; n++) { h[n] = 0.f; P[n] = 1.f; }
    float sdl = 0.f;

    size_t sidx = ((size_t)((b * DIN + d) * NCH + c)) * NST;
    if constexpr (PASS2) {
        #pragma unroll
        for (int n = 0; n < NST; n += 4) {
            float4 v = *(const float4*)(g_H0 + sidx + n);
            h[n] = v.x; h[n+1] = v.y; h[n+2] = v.z; h[n+3] = v.w;
        }
    }
    float Dp = PASS2 ? D_param[d] : 0.f;

    for (int t = 0; t < LC; t++) {
        size_t row = row0 + t;
        float dl = g_delta[row * DIN + d];
        float uv = __half2float(g_uh[row * DIN + d]);
        float du = dl * uv;

        float e[NST];
        if (structured) {
            float e1 = __expf(dl * A[0]);
            float e2 = e1 * e1, e4 = e2 * e2, e8 = e4 * e4;
            e[0]  = e1;           e[1]  = e2;           e[2]  = e2 * e1;
            e[3]  = e4;           e[4]  = e4 * e1;      e[5]  = e4 * e2;
            e[6]  = e4 * e2 * e1; e[7]  = e8;           e[8]  = e8 * e1;
            e[9]  = e8 * e2;      e[10] = e8 * e2 * e1; e[11] = e8 * e4;
            e[12] = e8 * e4 * e1; e[13] = e8 * e4 * e2; e[14] = e8 * e4 * e2 * e1;
            e[15] = e8 * e8;
            if constexpr (!PASS2) sdl += dl;
        } else {
            #pragma unroll
            for (int n = 0; n < NST; n++) e[n] = __expf(dl * A[n]);
            if constexpr (!PASS2) {
                #pragma unroll
                for (int n = 0; n < NST; n++) P[n] *= e[n];
            }
        }

        #pragma unroll
        for (int n = 0; n < NST; n++)
            h[n] = fmaf(e[n], h[n], du * sB[t][n]);

        if constexpr (PASS2) {
            float y = Dp * uv;
            #pragma unroll
            for (int n = 0; n < NST; n++) y = fmaf(h[n], sC[t][n], y);

            float z = __half2float(g_xzh[row * (size_t)(2 * DIN) + DIN + d]);
            float sz = z / (1.f + __expf(-z));
            g_gateh[row * DIN + d] = __float2half_rn(y * sz);
        }
    }

    if constexpr (!PASS2) {
        if (structured) {
            float p1 = __expf(sdl * A[0]);
            float p2 = p1 * p1, p4 = p2 * p2, p8 = p4 * p4;
            P[0]  = p1;           P[1]  = p2;           P[2]  = p2 * p1;
            P[3]  = p4;           P[4]  = p4 * p1;      P[5]  = p4 * p2;
            P[6]  = p4 * p2 * p1; P[7]  = p8;           P[8]  = p8 * p1;
            P[9]  = p8 * p2;      P[10] = p8 * p2 * p1; P[11] = p8 * p4;
            P[12] = p8 * p4 * p1; P[13] = p8 * p4 * p2; P[14] = p8 * p4 * p2 * p1;
            P[15] = p8 * p8;
        }
        #pragma unroll
        for (int n = 0; n < NST; n += 4) {
            float4 vp = { P[n], P[n+1], P[n+2], P[n+3] };
            float4 vh = { h[n], h[n+1], h[n+2], h[n+3] };
            *(float4*)(g_P + sidx + n)    = vp;
            *(float4*)(g_hloc + sidx + n) = vh;
        }
    }
}

__global__ void scan_combine_kernel()
{
    int gid = blockIdx.x * blockDim.x + threadIdx.x;
    if (gid >= BSZ * DIN) return;
    size_t base = (size_t)gid * NCH * NST;
    float H[NST];
    #pragma unroll
    for (int n = 0; n < NST; n++) H[n] = 0.f;
    for (int c = 0; c < NCH; c++) {
        size_t idx = base + (size_t)c * NST;
        #pragma unroll
        for (int n = 0; n < NST; n += 4) {
            float4 v = { H[n], H[n+1], H[n+2], H[n+3] };
            *(float4*)(g_H0 + idx + n) = v;
        }
        #pragma unroll
        for (int n = 0; n < NST; n++)
            H[n] = fmaf(g_P[idx + n], H[n], g_hloc[idx + n]);
    }
}

// ---------------------------------------------------------------------------
// Launch
// ---------------------------------------------------------------------------
extern "C" void kernel_launch(void* const* d_in, const int* in_sizes, int n_in,
                              void* d_out, int out_size)
{
    const float* x       = (const float*)d_in[0];
    const float* w_norm  = (const float*)d_in[1];
    const float* b_norm  = (const float*)d_in[2];
    const float* w_in    = (const float*)d_in[3];
    const float* w_conv  = (const float*)d_in[4];
    const float* b_conv  = (const float*)d_in[5];
    const float* A_log   = (const float*)d_in[6];
    const float* w_b     = (const float*)d_in[7];
    const float* w_c     = (const float*)d_in[8];
    const float* w_delta = (const float*)d_in[9];
    const float* b_delta = (const float*)d_in[10];
    const float* D_param = (const float*)d_in[11];
    const float* w_out   = (const float*)d_in[12];
    float* out = (float*)d_out;

    cudaFuncSetAttribute(tc_gemm<2 * DIN, DM, 0, 0>,
                         cudaFuncAttributeMaxDynamicSharedMemorySize, GEMM_DSMEM);
    cudaFuncSetAttribute(tc_gemm<N2, DIN, 3, 1>,
                         cudaFuncAttributeMaxDynamicSharedMemorySize, GEMM_DSMEM);
    cudaFuncSetAttribute(tc_gemm<DM, DIN, 2, 2>,
                         cudaFuncAttributeMaxDynamicSharedMemorySize, GEMM_DSMEM);

    __half *wt_in, *wt_d2, *wt_o;
    cudaGetSymbolAddress((void**)&wt_in, g_wtin);
    cudaGetSymbolAddress((void**)&wt_d2, g_wtd2);
    cudaGetSymbolAddress((void**)&wt_o,  g_wto);

    // 0+1. merged weight prep + layernorm (independent work, one launch)
    prep_ln_kernel<<<10248 + ROWS, 256>>>(w_in, w_delta, w_out, w_b, w_c,
                                          x, w_norm, b_norm);

    // 2. xz = xn @ w_in  (fp16 out)
    tc_gemm<2 * DIN, DM, 0, 0>
        <<<dim3((2 * DIN) / 128, ROWS / 128), 128, GEMM_DSMEM>>>(wt_in, nullptr, nullptr, nullptr);

    // 3. conv + silu -> uh
    conv_silu_kernel<<<(ROWS / CRPT) * (DIN / CCH) / 256, 256>>>(w_conv, b_conv);

    // 4. combined: delta = softplus(u@w_delta + b), Bseq, Cseq
    tc_gemm<N2, DIN, 3, 1>
        <<<dim3(N2 / 128, ROWS / 128), 128, GEMM_DSMEM>>>(wt_d2, b_delta, nullptr, nullptr);

    // 5. chunked selective scan
    scan_kernel<false><<<BSZ * NCH * (DIN / 128), 128>>>(A_log, D_param);
    scan_combine_kernel<<<(BSZ * DIN) / 256, 256>>>();
    scan_kernel<true><<<BSZ * NCH * (DIN / 128), 128>>>(A_log, D_param);

    // 6. out = gate @ w_out + residual
    tc_gemm<DM, DIN, 2, 2>
        <<<dim3(DM / 128, ROWS / 128), 128, GEMM_DSMEM>>>(wt_o, nullptr, x, out);
}